// round 7
// baseline (speedup 1.0000x reference)
#include <cuda_runtime.h>
#include <cstdint>

#define B_    4
#define CIN   128
#define COUT  128
#define H_    64
#define W_    64
#define T_    16
#define SS    512
#define NPOS  (H_ * W_ * T_)

// ---- static device scratch (no cudaMalloc allowed) ----
__device__ float g_s[B_ * CIN];
__device__ float g_w2[COUT * CIN];
__device__ float g_siginv[B_ * COUT];
__device__ float g_wt2[(size_t)B_ * 9 * CIN * COUT];  // [b][tap][ci][cout], tf32(w*s)

__device__ __forceinline__ float tf32r(float x) {
    unsigned u;
    asm("cvt.rna.tf32.f32 %0, %1;" : "=r"(u) : "f"(x));
    return __uint_as_float(u);
}

__device__ __forceinline__ uint32_t smem_u32(const void* p) {
    uint32_t a;
    asm("{ .reg .u64 t; cvta.to.shared.u64 t, %1; cvt.u32.u64 %0, t; }" : "=r"(a) : "l"(p));
    return a;
}

__device__ __forceinline__ void cp16(uint32_t dst, const float* src) {
    asm volatile("cp.async.cg.shared.global [%0], [%1], 16;"
                 :: "r"(dst), "l"(src) : "memory");
}

// ---------------------------------------------------------------------------
// Prologue kernels
// ---------------------------------------------------------------------------
__global__ void k_style(const float* __restrict__ style,
                        const float* __restrict__ style_w,
                        const float* __restrict__ style_b) {
    int wg = blockIdx.x * 8 + (threadIdx.x >> 5);
    int lane = threadIdx.x & 31;
    int b = wg >> 7, i = wg & 127;
    const float* st = style + (size_t)b * SS;
    const float* sw = style_w + (size_t)i * SS;
    float acc = 0.f;
#pragma unroll
    for (int r = 0; r < 16; ++r) acc += st[lane + 32 * r] * sw[lane + 32 * r];
#pragma unroll
    for (int o = 16; o; o >>= 1) acc += __shfl_xor_sync(~0u, acc, o);
    if (lane == 0) g_s[b * CIN + i] = acc + style_b[i];
}

// g_wt2[b][tap][ci][cout] = tf32(w[cout][ci][tap] * s[b][ci]); g_w2 once
__global__ void k_wmod(const float* __restrict__ weight) {
    int ci = blockIdx.x, b = blockIdx.y, o = threadIdx.x;
    float s = g_s[b * CIN + ci];
    float wsq = 0.f;
#pragma unroll
    for (int tap = 0; tap < 9; ++tap) {
        float w = weight[((size_t)o * CIN + ci) * 9 + tap];
        wsq += w * w;
        g_wt2[(((size_t)b * 9 + tap) * CIN + ci) * COUT + o] = tf32r(w * s);
    }
    if (b == 0) g_w2[o * CIN + ci] = wsq;
}

__global__ void k_sig2() {
    int wg = blockIdx.x * 8 + (threadIdx.x >> 5);
    int lane = threadIdx.x & 31;
    int b = wg >> 7, o = wg & 127;
    float acc = 0.f;
#pragma unroll
    for (int r = 0; r < 4; ++r) {
        int i = lane + 32 * r;
        float s = g_s[b * CIN + i];
        acc += g_w2[o * CIN + i] * s * s;
    }
#pragma unroll
    for (int off = 16; off; off >>= 1) acc += __shfl_xor_sync(~0u, acc, off);
    if (lane == 0) g_siginv[b * COUT + o] = rsqrtf(acc + 1e-8f);
}

// ---------------------------------------------------------------------------
// Main conv: implicit GEMM, tf32 mma.sync m16n8k8, double-buffered.
// CTA 256 thr = 8 warps (2M x 4N), warp tile 64x64. CTA tile M=128 x N=256
// (16 w x 16 t at fixed b,h). 16 ci-chunks of 8.
// A (weights) via cp.async from pre-rounded g_wt2; X via LDG->tf32->STS.
// ---------------------------------------------------------------------------
#define SA_STRIDE 136                        // 136 mod 32 = 8 -> conflict-free
#define SX_STRIDE 872                        // 864 (3dh*18w*16t) + 8; mod 32 = 8
#define SA_FLOATS (72 * SA_STRIDE)           // 9792
#define SX_FLOATS (8 * SX_STRIDE)            // 6976
#define STAGE_FLOATS (SA_FLOATS + SX_FLOATS) // 16768
#define SMEM_BYTES (2 * STAGE_FLOATS * 4)    // 134144

__global__ void __launch_bounds__(256, 1)
k_conv(const float* __restrict__ x,
       const float* __restrict__ noise,
       const float* __restrict__ noise_param,
       const float* __restrict__ bias_param,
       float* __restrict__ out) {
    extern __shared__ float smem[];
    const uint32_t sb = smem_u32(smem);

    const int tid  = threadIdx.x;
    const int lane = tid & 31;
    const int wid  = tid >> 5;
    const int g    = lane >> 2;
    const int q    = lane & 3;
    const int mwarp = (wid >> 2) * 64;
    const int nwarp = (wid & 3) * 64;

    const int bid = blockIdx.x;
    const int b  = bid >> 8;
    const int h  = (bid >> 2) & 63;
    const int w0 = (bid & 3) * 16;

    float acc[4][8][4];
#pragma unroll
    for (int mf = 0; mf < 4; ++mf)
#pragma unroll
        for (int nf = 0; nf < 8; ++nf)
#pragma unroll
            for (int r = 0; r < 4; ++r) acc[mf][nf][r] = 0.f;

    // ---- stage chunk c (8 ci) into stage buffer s ----
    auto stage_a = [&](int c, int s) {
        const int c0 = c * 8;
        const uint32_t sa = sb + (uint32_t)(s * STAGE_FLOATS) * 4;
        // A: 72 rows (tap*8+k) x 128 couts = 2304 x 16B, 9 per thread
#pragma unroll
        for (int i = 0; i < 9; ++i) {
            int li  = tid + i * 256;
            int row = li >> 5;
            int seg = li & 31;
            int tap = row >> 3, k = row & 7;
            const float* src = g_wt2 +
                (((size_t)(b * 9 + tap) * CIN) + c0 + k) * COUT + seg * 4;
            cp16(sa + (uint32_t)(row * SA_STRIDE + seg * 4) * 4, src);
        }
    };
    auto stage_x = [&](int c, int s) {
        const int c0 = c * 8;
        float* sx = smem + s * STAGE_FLOATS + SA_FLOATS;
        // X: 8 ci x 54 pos (3dh x 18wl) x 4 t4-segs = 1728 x 16B
        for (int li = tid; li < 1728; li += 256) {
            int ci  = li / 216;
            int r   = li - ci * 216;
            int pos = r >> 2;
            int t4  = (r & 3) << 2;
            int dh  = pos / 18;
            int wl  = pos - dh * 18;
            int gh  = h + dh - 1;
            int gw  = w0 + wl - 1;
            float4 v = make_float4(0.f, 0.f, 0.f, 0.f);
            if (((unsigned)gh < (unsigned)H_) & ((unsigned)gw < (unsigned)W_)) {
                v = *reinterpret_cast<const float4*>(
                    x + ((((size_t)b * CIN + c0 + ci) * H_ + gh) * W_ + gw) * T_ + t4);
                v.x = tf32r(v.x); v.y = tf32r(v.y);
                v.z = tf32r(v.z); v.w = tf32r(v.w);
            }
            *reinterpret_cast<float4*>(sx + ci * SX_STRIDE + pos * 16 + t4) = v;
        }
    };

    auto compute = [&](int s) {
        const float* sA = smem + s * STAGE_FLOATS;
        const float* sX = sA + SA_FLOATS;
#pragma unroll
        for (int kh = 0; kh < 3; ++kh) {
            // 12 shared B-frag pairs cover warp's 64 N + two kw shifts of 16
            unsigned b0[12], b1[12];
            const float* bp = sX + q * SX_STRIDE + kh * 288 + nwarp + g;
#pragma unroll
            for (int f = 0; f < 12; ++f) {
                b0[f] = __float_as_uint(bp[f * 8]);
                b1[f] = __float_as_uint(bp[f * 8 + 4 * SX_STRIDE]);
            }
#pragma unroll
            for (int kw = 0; kw < 3; ++kw) {
                const int t8 = (kh * 3 + kw) * 8;
                unsigned a[4][4];
                const float* ap = sA + (t8 + q) * SA_STRIDE + mwarp + g;
#pragma unroll
                for (int mf = 0; mf < 4; ++mf) {
                    const float* p = ap + mf * 16;
                    a[mf][0] = __float_as_uint(p[0]);
                    a[mf][1] = __float_as_uint(p[8]);
                    a[mf][2] = __float_as_uint(p[4 * SA_STRIDE]);
                    a[mf][3] = __float_as_uint(p[4 * SA_STRIDE + 8]);
                }
#pragma unroll
                for (int mf = 0; mf < 4; ++mf) {
#pragma unroll
                    for (int nf = 0; nf < 8; ++nf) {
                        const int f = kw * 2 + nf;
                        asm volatile(
                            "mma.sync.aligned.m16n8k8.row.col.f32.tf32.tf32.f32 "
                            "{%0,%1,%2,%3}, {%4,%5,%6,%7}, {%8,%9}, {%0,%1,%2,%3};"
                            : "+f"(acc[mf][nf][0]), "+f"(acc[mf][nf][1]),
                              "+f"(acc[mf][nf][2]), "+f"(acc[mf][nf][3])
                            : "r"(a[mf][0]), "r"(a[mf][1]), "r"(a[mf][2]), "r"(a[mf][3]),
                              "r"(b0[f]), "r"(b1[f]));
                    }
                }
            }
        }
    };

    // ---- pipelined mainloop (double buffer, 2 syncs per chunk) ----
    stage_a(0, 0);
    asm volatile("cp.async.commit_group;" ::: "memory");
    stage_x(0, 0);
#pragma unroll 1
    for (int c = 0; c < 16; ++c) {
        if (c < 15) {
            stage_a(c + 1, (c + 1) & 1);
            asm volatile("cp.async.commit_group;" ::: "memory");
            stage_x(c + 1, (c + 1) & 1);
            asm volatile("cp.async.wait_group 1;" ::: "memory");
        } else {
            asm volatile("cp.async.wait_group 0;" ::: "memory");
        }
        __syncthreads();
        compute(c & 1);
        __syncthreads();
    }

    // ---- epilogue: demodulate + noise + bias ----
    float si[4][2], np[4][2], bp2[4][2];
#pragma unroll
    for (int mf = 0; mf < 4; ++mf)
#pragma unroll
        for (int hf = 0; hf < 2; ++hf) {
            int m = mwarp + mf * 16 + g + hf * 8;
            si[mf][hf]  = g_siginv[b * COUT + m];
            np[mf][hf]  = noise_param[m];
            bp2[mf][hf] = bias_param[m];
        }
#pragma unroll
    for (int nf = 0; nf < 8; ++nf) {
        int n  = nwarp + nf * 8 + q * 2;
        int wl = n >> 4;
        int t  = n & 15;
        float2 nz = *reinterpret_cast<const float2*>(
            noise + (((size_t)b * H_ + h) * W_ + w0 + wl) * T_ + t);
#pragma unroll
        for (int mf = 0; mf < 4; ++mf) {
#pragma unroll
            for (int hf = 0; hf < 2; ++hf) {
                int m = mwarp + mf * 16 + g + hf * 8;
                float2 r;
                r.x = acc[mf][nf][hf * 2 + 0] * si[mf][hf] + np[mf][hf] * nz.x + bp2[mf][hf];
                r.y = acc[mf][nf][hf * 2 + 1] * si[mf][hf] + np[mf][hf] * nz.y + bp2[mf][hf];
                *reinterpret_cast<float2*>(
                    out + ((((size_t)b * COUT + m) * H_ + h) * W_ + w0 + wl) * T_ + t) = r;
            }
        }
    }
}

// ---------------------------------------------------------------------------
// Launch. inputs: x, style, noise, weight, style_w, style_b, noise_param,
//                 bias_param
// ---------------------------------------------------------------------------
extern "C" void kernel_launch(void* const* d_in, const int* in_sizes, int n_in,
                              void* d_out, int out_size) {
    const float* x           = (const float*)d_in[0];
    const float* style       = (const float*)d_in[1];
    const float* noise       = (const float*)d_in[2];
    const float* weight      = (const float*)d_in[3];
    const float* style_w     = (const float*)d_in[4];
    const float* style_b     = (const float*)d_in[5];
    const float* noise_param = (const float*)d_in[6];
    const float* bias_param  = (const float*)d_in[7];
    float* out = (float*)d_out;

    k_style<<<64, 256>>>(style, style_w, style_b);
    k_wmod<<<dim3(CIN, B_), COUT>>>(weight);
    k_sig2<<<64, 256>>>();

    cudaFuncSetAttribute(k_conv, cudaFuncAttributeMaxDynamicSharedMemorySize,
                         SMEM_BYTES);
    k_conv<<<1024, 256, SMEM_BYTES>>>(x, noise, noise_param, bias_param, out);
}

// round 8
// speedup vs baseline: 1.3702x; 1.3702x over previous
#include <cuda_runtime.h>
#include <cstdint>

#define B_    4
#define CIN   128
#define COUT  128
#define H_    64
#define W_    64
#define T_    16
#define SS    512
#define NPOS  (H_ * W_ * T_)

// ---- static device scratch (no cudaMalloc allowed) ----
__device__ float g_s[B_ * CIN];
__device__ float g_w2[COUT * CIN];
__device__ float g_siginv[B_ * COUT];
__device__ float g_wt2[(size_t)B_ * 9 * CIN * COUT];  // [b][tap][ci][cout], tf32(w*s)

__device__ __forceinline__ float tf32r(float x) {
    unsigned u;
    asm("cvt.rna.tf32.f32 %0, %1;" : "=r"(u) : "f"(x));
    return __uint_as_float(u);
}

__device__ __forceinline__ uint32_t smem_u32(const void* p) {
    uint32_t a;
    asm("{ .reg .u64 t; cvta.to.shared.u64 t, %1; cvt.u32.u64 %0, t; }" : "=r"(a) : "l"(p));
    return a;
}

__device__ __forceinline__ void cp16(uint32_t dst, const float* src) {
    asm volatile("cp.async.cg.shared.global [%0], [%1], 16;"
                 :: "r"(dst), "l"(src) : "memory");
}

// ---------------------------------------------------------------------------
// Prologue kernels
// ---------------------------------------------------------------------------
__global__ void k_style(const float* __restrict__ style,
                        const float* __restrict__ style_w,
                        const float* __restrict__ style_b) {
    int wg = blockIdx.x * 8 + (threadIdx.x >> 5);
    int lane = threadIdx.x & 31;
    int b = wg >> 7, i = wg & 127;
    const float* st = style + (size_t)b * SS;
    const float* sw = style_w + (size_t)i * SS;
    float acc = 0.f;
#pragma unroll
    for (int r = 0; r < 16; ++r) acc += st[lane + 32 * r] * sw[lane + 32 * r];
#pragma unroll
    for (int o = 16; o; o >>= 1) acc += __shfl_xor_sync(~0u, acc, o);
    if (lane == 0) g_s[b * CIN + i] = acc + style_b[i];
}

// g_wt2[b][tap][ci][cout] = tf32(w[cout][ci][tap] * s[b][ci]); g_w2 once
__global__ void k_wmod(const float* __restrict__ weight) {
    int ci = blockIdx.x, b = blockIdx.y, o = threadIdx.x;
    float s = g_s[b * CIN + ci];
    float wsq = 0.f;
#pragma unroll
    for (int tap = 0; tap < 9; ++tap) {
        float w = weight[((size_t)o * CIN + ci) * 9 + tap];
        wsq += w * w;
        g_wt2[(((size_t)b * 9 + tap) * CIN + ci) * COUT + o] = tf32r(w * s);
    }
    if (b == 0) g_w2[o * CIN + ci] = wsq;
}

__global__ void k_sig2() {
    int wg = blockIdx.x * 8 + (threadIdx.x >> 5);
    int lane = threadIdx.x & 31;
    int b = wg >> 7, o = wg & 127;
    float acc = 0.f;
#pragma unroll
    for (int r = 0; r < 4; ++r) {
        int i = lane + 32 * r;
        float s = g_s[b * CIN + i];
        acc += g_w2[o * CIN + i] * s * s;
    }
#pragma unroll
    for (int off = 16; off; off >>= 1) acc += __shfl_xor_sync(~0u, acc, off);
    if (lane == 0) g_siginv[b * COUT + o] = rsqrtf(acc + 1e-8f);
}

// ---------------------------------------------------------------------------
// Main conv: implicit GEMM, tf32 mma.sync m16n8k8, cp.async double-buffered.
// CTA 128 thr = 4 warps (2M x 2N), warp tile 64x64. CTA tile M=128 x N=128
// (8 w x 16 t at fixed b,h). 16 ci-chunks of 8.
// A (weights) via cp.async from pre-rounded g_wt2; X via LDG->tf32->STS.
// ---------------------------------------------------------------------------
#define SA_STRIDE 136
#define SX_STRIDE 488
#define SA_FLOATS (72 * SA_STRIDE)           // 9792
#define SX_FLOATS (8 * SX_STRIDE)            // 3904
#define STAGE_FLOATS (SA_FLOATS + SX_FLOATS) // 13696
#define SMEM_BYTES (2 * STAGE_FLOATS * 4)    // 109568

__global__ void __launch_bounds__(128)
k_conv(const float* __restrict__ x,
       const float* __restrict__ noise,
       const float* __restrict__ noise_param,
       const float* __restrict__ bias_param,
       float* __restrict__ out) {
    extern __shared__ float smem[];
    const uint32_t sb = smem_u32(smem);

    const int tid  = threadIdx.x;
    const int lane = tid & 31;
    const int wid  = tid >> 5;
    const int g    = lane >> 2;
    const int q    = lane & 3;
    const int mwarp = (wid >> 1) * 64;
    const int nwarp = (wid & 1) * 64;

    const int bid = blockIdx.x;
    const int b  = bid >> 9;
    const int h  = (bid >> 3) & 63;
    const int w0 = (bid & 7) * 8;

    float acc[4][8][4];
#pragma unroll
    for (int mf = 0; mf < 4; ++mf)
#pragma unroll
        for (int nf = 0; nf < 8; ++nf)
#pragma unroll
            for (int r = 0; r < 4; ++r) acc[mf][nf][r] = 0.f;

    // ---- stage chunk c (8 ci): A via cp.async, X via LDG->tf32->STS ----
    auto stage_a = [&](int c, int s) {
        const int c0 = c * 8;
        const uint32_t sa = sb + (uint32_t)(s * STAGE_FLOATS) * 4;
        // A: 72 rows (tap*8+k) x 128 couts = 2304 x 16B, 18 per thread
#pragma unroll
        for (int i = 0; i < 18; ++i) {
            int li  = tid + i * 128;
            int row = li >> 5;
            int seg = li & 31;
            int tap = row >> 3, k = row & 7;
            const float* src = g_wt2 +
                (((size_t)(b * 9 + tap) * CIN) + c0 + k) * COUT + seg * 4;
            cp16(sa + (uint32_t)(row * SA_STRIDE + seg * 4) * 4, src);
        }
    };
    auto stage_x = [&](int c, int s) {
        const int c0 = c * 8;
        float* sx = smem + s * STAGE_FLOATS + SA_FLOATS;
        // X: 8 ci x 30 pos (3dh x 10wl) x 4 t4-segs = 960 x 16B
#pragma unroll
        for (int i = 0; i < 8; ++i) {
            int li  = tid + i * 128;
            if (li >= 960) break;
            int ci  = li / 120;
            int r   = li - ci * 120;
            int pos = r >> 2;
            int t4  = (r & 3) << 2;
            int dh  = pos / 10;
            int wl  = pos - dh * 10;
            int gh  = h + dh - 1;
            int gw  = w0 + wl - 1;
            float4 v = make_float4(0.f, 0.f, 0.f, 0.f);
            if (((unsigned)gh < (unsigned)H_) & ((unsigned)gw < (unsigned)W_)) {
                v = *reinterpret_cast<const float4*>(
                    x + ((((size_t)b * CIN + c0 + ci) * H_ + gh) * W_ + gw) * T_ + t4);
                v.x = tf32r(v.x); v.y = tf32r(v.y);
                v.z = tf32r(v.z); v.w = tf32r(v.w);
            }
            *reinterpret_cast<float4*>(sx + ci * SX_STRIDE + pos * 16 + t4) = v;
        }
    };

    auto compute = [&](int s) {
        const float* sA = smem + s * STAGE_FLOATS;
        const float* sX = sA + SA_FLOATS;
#pragma unroll
        for (int kh = 0; kh < 3; ++kh) {
            // 12 shared B-frag pairs cover all 3 kw shifts
            unsigned b0[12], b1[12];
            const float* bp = sX + q * SX_STRIDE + kh * 160 + nwarp + g;
#pragma unroll
            for (int f = 0; f < 12; ++f) {
                b0[f] = __float_as_uint(bp[f * 8]);
                b1[f] = __float_as_uint(bp[f * 8 + 4 * SX_STRIDE]);
            }
#pragma unroll
            for (int kw = 0; kw < 3; ++kw) {
                const int t8 = (kh * 3 + kw) * 8;
                unsigned a[4][4];
                const float* ap = sA + (t8 + q) * SA_STRIDE + mwarp + g;
#pragma unroll
                for (int mf = 0; mf < 4; ++mf) {
                    const float* p = ap + mf * 16;
                    a[mf][0] = __float_as_uint(p[0]);
                    a[mf][1] = __float_as_uint(p[8]);
                    a[mf][2] = __float_as_uint(p[4 * SA_STRIDE]);
                    a[mf][3] = __float_as_uint(p[4 * SA_STRIDE + 8]);
                }
#pragma unroll
                for (int mf = 0; mf < 4; ++mf) {
#pragma unroll
                    for (int nf = 0; nf < 8; ++nf) {
                        const int f = kw * 2 + nf;
                        asm volatile(
                            "mma.sync.aligned.m16n8k8.row.col.f32.tf32.tf32.f32 "
                            "{%0,%1,%2,%3}, {%4,%5,%6,%7}, {%8,%9}, {%0,%1,%2,%3};"
                            : "+f"(acc[mf][nf][0]), "+f"(acc[mf][nf][1]),
                              "+f"(acc[mf][nf][2]), "+f"(acc[mf][nf][3])
                            : "r"(a[mf][0]), "r"(a[mf][1]), "r"(a[mf][2]), "r"(a[mf][3]),
                              "r"(b0[f]), "r"(b1[f]));
                    }
                }
            }
        }
    };

    // ---- pipelined mainloop ----
    stage_a(0, 0);
    asm volatile("cp.async.commit_group;" ::: "memory");
    stage_x(0, 0);
#pragma unroll 1
    for (int c = 0; c < 16; ++c) {
        if (c < 15) {
            stage_a(c + 1, (c + 1) & 1);
            asm volatile("cp.async.commit_group;" ::: "memory");
            stage_x(c + 1, (c + 1) & 1);
            asm volatile("cp.async.wait_group 1;" ::: "memory");
        } else {
            asm volatile("cp.async.wait_group 0;" ::: "memory");
        }
        __syncthreads();
        compute(c & 1);
        __syncthreads();
    }

    // ---- epilogue: demodulate + noise + bias ----
    float si[4][2], np[4][2], bp2[4][2];
#pragma unroll
    for (int mf = 0; mf < 4; ++mf)
#pragma unroll
        for (int hf = 0; hf < 2; ++hf) {
            int m = mwarp + mf * 16 + g + hf * 8;
            si[mf][hf]  = g_siginv[b * COUT + m];
            np[mf][hf]  = noise_param[m];
            bp2[mf][hf] = bias_param[m];
        }
#pragma unroll
    for (int nf = 0; nf < 8; ++nf) {
        int n  = nwarp + nf * 8 + q * 2;
        int wl = n >> 4;
        int t  = n & 15;
        float2 nz = *reinterpret_cast<const float2*>(
            noise + (((size_t)b * H_ + h) * W_ + w0 + wl) * T_ + t);
#pragma unroll
        for (int mf = 0; mf < 4; ++mf) {
#pragma unroll
            for (int hf = 0; hf < 2; ++hf) {
                int m = mwarp + mf * 16 + g + hf * 8;
                float2 r;
                r.x = acc[mf][nf][hf * 2 + 0] * si[mf][hf] + np[mf][hf] * nz.x + bp2[mf][hf];
                r.y = acc[mf][nf][hf * 2 + 1] * si[mf][hf] + np[mf][hf] * nz.y + bp2[mf][hf];
                *reinterpret_cast<float2*>(
                    out + ((((size_t)b * COUT + m) * H_ + h) * W_ + w0 + wl) * T_ + t) = r;
            }
        }
    }
}

// ---------------------------------------------------------------------------
// Launch. inputs: x, style, noise, weight, style_w, style_b, noise_param,
//                 bias_param
// ---------------------------------------------------------------------------
extern "C" void kernel_launch(void* const* d_in, const int* in_sizes, int n_in,
                              void* d_out, int out_size) {
    const float* x           = (const float*)d_in[0];
    const float* style       = (const float*)d_in[1];
    const float* noise       = (const float*)d_in[2];
    const float* weight      = (const float*)d_in[3];
    const float* style_w     = (const float*)d_in[4];
    const float* style_b     = (const float*)d_in[5];
    const float* noise_param = (const float*)d_in[6];
    const float* bias_param  = (const float*)d_in[7];
    float* out = (float*)d_out;

    k_style<<<64, 256>>>(style, style_w, style_b);
    k_wmod<<<dim3(CIN, B_), COUT>>>(weight);
    k_sig2<<<64, 256>>>();

    cudaFuncSetAttribute(k_conv, cudaFuncAttributeMaxDynamicSharedMemorySize,
                         SMEM_BYTES);
    k_conv<<<2048, 128, SMEM_BYTES>>>(x, noise, noise_param, bias_param, out);
}

// round 9
// speedup vs baseline: 1.8213x; 1.3292x over previous
#include <cuda_runtime.h>
#include <cstdint>

#define B_    4
#define CIN   128
#define COUT  128
#define H_    64
#define W_    64
#define T_    16
#define SS    512
#define NPOS  (H_ * W_ * T_)

// ---- static device scratch (no cudaMalloc allowed) ----
__device__ float g_s[B_ * CIN];
__device__ float g_w2[COUT * CIN];
__device__ float g_siginv[B_ * COUT];
__device__ float g_wt2[(size_t)B_ * 9 * CIN * COUT];  // [b][tap][ci][cout], tf32(w*s)

__device__ __forceinline__ float tf32r(float x) {
    unsigned u;
    asm("cvt.rna.tf32.f32 %0, %1;" : "=r"(u) : "f"(x));
    return __uint_as_float(u);
}

__device__ __forceinline__ unsigned tf32ru(float x) {
    unsigned u;
    asm("cvt.rna.tf32.f32 %0, %1;" : "=r"(u) : "f"(x));
    return u;
}

__device__ __forceinline__ uint32_t smem_u32(const void* p) {
    uint32_t a;
    asm("{ .reg .u64 t; cvta.to.shared.u64 t, %1; cvt.u32.u64 %0, t; }" : "=r"(a) : "l"(p));
    return a;
}

__device__ __forceinline__ void cp16(uint32_t dst, const float* src) {
    asm volatile("cp.async.cg.shared.global [%0], [%1], 16;"
                 :: "r"(dst), "l"(src) : "memory");
}
__device__ __forceinline__ void cp16p(uint32_t dst, const float* src, int ok) {
    asm volatile("cp.async.cg.shared.global [%0], [%1], 16, %2;"
                 :: "r"(dst), "l"(src), "r"(ok ? 16 : 0) : "memory");
}

// ---------------------------------------------------------------------------
// Prologue kernels
// ---------------------------------------------------------------------------
__global__ void k_style(const float* __restrict__ style,
                        const float* __restrict__ style_w,
                        const float* __restrict__ style_b) {
    int wg = blockIdx.x * 8 + (threadIdx.x >> 5);
    int lane = threadIdx.x & 31;
    int b = wg >> 7, i = wg & 127;
    const float* st = style + (size_t)b * SS;
    const float* sw = style_w + (size_t)i * SS;
    float acc = 0.f;
#pragma unroll
    for (int r = 0; r < 16; ++r) acc += st[lane + 32 * r] * sw[lane + 32 * r];
#pragma unroll
    for (int o = 16; o; o >>= 1) acc += __shfl_xor_sync(~0u, acc, o);
    if (lane == 0) g_s[b * CIN + i] = acc + style_b[i];
}

// g_wt2[b][tap][ci][cout] = tf32(w[cout][ci][tap] * s[b][ci]); g_w2 once
__global__ void k_wmod(const float* __restrict__ weight) {
    int ci = blockIdx.x, b = blockIdx.y, o = threadIdx.x;
    float s = g_s[b * CIN + ci];
    float wsq = 0.f;
#pragma unroll
    for (int tap = 0; tap < 9; ++tap) {
        float w = weight[((size_t)o * CIN + ci) * 9 + tap];
        wsq += w * w;
        g_wt2[(((size_t)b * 9 + tap) * CIN + ci) * COUT + o] = tf32r(w * s);
    }
    if (b == 0) g_w2[o * CIN + ci] = wsq;
}

__global__ void k_sig2() {
    int wg = blockIdx.x * 8 + (threadIdx.x >> 5);
    int lane = threadIdx.x & 31;
    int b = wg >> 7, o = wg & 127;
    float acc = 0.f;
#pragma unroll
    for (int r = 0; r < 4; ++r) {
        int i = lane + 32 * r;
        float s = g_s[b * CIN + i];
        acc += g_w2[o * CIN + i] * s * s;
    }
#pragma unroll
    for (int off = 16; off; off >>= 1) acc += __shfl_xor_sync(~0u, acc, off);
    if (lane == 0) g_siginv[b * COUT + o] = rsqrtf(acc + 1e-8f);
}

// ---------------------------------------------------------------------------
// Main conv: implicit GEMM, tf32 mma.sync m16n8k8, cp.async double-buffered.
// CTA 128 thr = 4 warps (2M x 2N), warp tile 64x64. CTA tile M=128 x N=128
// (8 w x 16 t at fixed b,h). 16 ci-chunks of 8.
// A via cp.async from pre-rounded g_wt2; X via cp.async RAW f32, with
// rna->tf32 rounding applied to B fragments in registers (same numerics).
// ---------------------------------------------------------------------------
#define SA_STRIDE 136
#define SX_STRIDE 488
#define SA_FLOATS (72 * SA_STRIDE)           // 9792
#define SX_FLOATS (8 * SX_STRIDE)            // 3904
#define STAGE_FLOATS (SA_FLOATS + SX_FLOATS) // 13696
#define SMEM_BYTES (2 * STAGE_FLOATS * 4)    // 109568

__global__ void __launch_bounds__(128)
k_conv(const float* __restrict__ x,
       const float* __restrict__ noise,
       const float* __restrict__ noise_param,
       const float* __restrict__ bias_param,
       float* __restrict__ out) {
    extern __shared__ float smem[];
    const uint32_t sb = smem_u32(smem);

    const int tid  = threadIdx.x;
    const int lane = tid & 31;
    const int wid  = tid >> 5;
    const int g    = lane >> 2;
    const int q    = lane & 3;
    const int mwarp = (wid >> 1) * 64;
    const int nwarp = (wid & 1) * 64;

    const int bid = blockIdx.x;
    const int b  = bid >> 9;
    const int h  = (bid >> 3) & 63;
    const int w0 = (bid & 7) * 8;

    float acc[4][8][4];
#pragma unroll
    for (int mf = 0; mf < 4; ++mf)
#pragma unroll
        for (int nf = 0; nf < 8; ++nf)
#pragma unroll
            for (int r = 0; r < 4; ++r) acc[mf][nf][r] = 0.f;

    // ---- stage chunk c (8 ci): both A and X via cp.async ----
    auto stage_load = [&](int c, int s) {
        const int c0 = c * 8;
        const uint32_t sa = sb + (uint32_t)(s * STAGE_FLOATS) * 4;
        const uint32_t sx = sa + SA_FLOATS * 4;
        // A: 72 rows (tap*8+k) x 128 couts = 2304 x 16B, 18 per thread
#pragma unroll
        for (int i = 0; i < 18; ++i) {
            int li  = tid + i * 128;
            int row = li >> 5;
            int seg = li & 31;
            int tap = row >> 3, k = row & 7;
            const float* src = g_wt2 +
                (((size_t)(b * 9 + tap) * CIN) + c0 + k) * COUT + seg * 4;
            cp16(sa + (uint32_t)(row * SA_STRIDE + seg * 4) * 4, src);
        }
        // X: 8 ci x 30 pos x 4 segs = 960 x 16B (zfill OOB), raw f32
        for (int li = tid; li < 960; li += 128) {
            int ci  = li / 120;
            int r   = li - ci * 120;
            int pos = r >> 2;
            int t4  = (r & 3) << 2;
            int dh  = pos / 10;
            int wl  = pos - dh * 10;
            int gh  = h + dh - 1;
            int gw  = w0 + wl - 1;
            int ok  = ((unsigned)gh < (unsigned)H_) & ((unsigned)gw < (unsigned)W_);
            int ghc = ok ? gh : 0;
            int gwc = ok ? gw : 0;
            const float* src = x +
                ((((size_t)b * CIN + c0 + ci) * H_ + ghc) * W_ + gwc) * T_ + t4;
            cp16p(sx + (uint32_t)(ci * SX_STRIDE + pos * 16 + t4) * 4, src, ok);
        }
    };

    auto compute = [&](int s) {
        const float* sA = smem + s * STAGE_FLOATS;
        const float* sX = sA + SA_FLOATS;
#pragma unroll
        for (int kh = 0; kh < 3; ++kh) {
            // 12 shared B-frag pairs cover all 3 kw shifts; round in regs
            unsigned b0[12], b1[12];
            const float* bp = sX + q * SX_STRIDE + kh * 160 + nwarp + g;
#pragma unroll
            for (int f = 0; f < 12; ++f) {
                b0[f] = tf32ru(bp[f * 8]);
                b1[f] = tf32ru(bp[f * 8 + 4 * SX_STRIDE]);
            }
#pragma unroll
            for (int kw = 0; kw < 3; ++kw) {
                const int t8 = (kh * 3 + kw) * 8;
                unsigned a[4][4];
                const float* ap = sA + (t8 + q) * SA_STRIDE + mwarp + g;
#pragma unroll
                for (int mf = 0; mf < 4; ++mf) {
                    const float* p = ap + mf * 16;
                    a[mf][0] = __float_as_uint(p[0]);
                    a[mf][1] = __float_as_uint(p[8]);
                    a[mf][2] = __float_as_uint(p[4 * SA_STRIDE]);
                    a[mf][3] = __float_as_uint(p[4 * SA_STRIDE + 8]);
                }
#pragma unroll
                for (int mf = 0; mf < 4; ++mf) {
#pragma unroll
                    for (int nf = 0; nf < 8; ++nf) {
                        const int f = kw * 2 + nf;
                        asm volatile(
                            "mma.sync.aligned.m16n8k8.row.col.f32.tf32.tf32.f32 "
                            "{%0,%1,%2,%3}, {%4,%5,%6,%7}, {%8,%9}, {%0,%1,%2,%3};"
                            : "+f"(acc[mf][nf][0]), "+f"(acc[mf][nf][1]),
                              "+f"(acc[mf][nf][2]), "+f"(acc[mf][nf][3])
                            : "r"(a[mf][0]), "r"(a[mf][1]), "r"(a[mf][2]), "r"(a[mf][3]),
                              "r"(b0[f]), "r"(b1[f]));
                    }
                }
            }
        }
    };

    // ---- pipelined mainloop ----
    stage_load(0, 0);
    asm volatile("cp.async.commit_group;" ::: "memory");
#pragma unroll 1
    for (int c = 0; c < 16; ++c) {
        if (c < 15) {
            stage_load(c + 1, (c + 1) & 1);
            asm volatile("cp.async.commit_group;" ::: "memory");
            asm volatile("cp.async.wait_group 1;" ::: "memory");
        } else {
            asm volatile("cp.async.wait_group 0;" ::: "memory");
        }
        __syncthreads();
        compute(c & 1);
        __syncthreads();
    }

    // ---- epilogue: demodulate + noise + bias ----
    float si[4][2], np[4][2], bp2[4][2];
#pragma unroll
    for (int mf = 0; mf < 4; ++mf)
#pragma unroll
        for (int hf = 0; hf < 2; ++hf) {
            int m = mwarp + mf * 16 + g + hf * 8;
            si[mf][hf]  = g_siginv[b * COUT + m];
            np[mf][hf]  = noise_param[m];
            bp2[mf][hf] = bias_param[m];
        }
#pragma unroll
    for (int nf = 0; nf < 8; ++nf) {
        int n  = nwarp + nf * 8 + q * 2;
        int wl = n >> 4;
        int t  = n & 15;
        float2 nz = *reinterpret_cast<const float2*>(
            noise + (((size_t)b * H_ + h) * W_ + w0 + wl) * T_ + t);
#pragma unroll
        for (int mf = 0; mf < 4; ++mf) {
#pragma unroll
            for (int hf = 0; hf < 2; ++hf) {
                int m = mwarp + mf * 16 + g + hf * 8;
                float2 r;
                r.x = acc[mf][nf][hf * 2 + 0] * si[mf][hf] + np[mf][hf] * nz.x + bp2[mf][hf];
                r.y = acc[mf][nf][hf * 2 + 1] * si[mf][hf] + np[mf][hf] * nz.y + bp2[mf][hf];
                *reinterpret_cast<float2*>(
                    out + ((((size_t)b * COUT + m) * H_ + h) * W_ + w0 + wl) * T_ + t) = r;
            }
        }
    }
}

// ---------------------------------------------------------------------------
// Launch. inputs: x, style, noise, weight, style_w, style_b, noise_param,
//                 bias_param
// ---------------------------------------------------------------------------
extern "C" void kernel_launch(void* const* d_in, const int* in_sizes, int n_in,
                              void* d_out, int out_size) {
    const float* x           = (const float*)d_in[0];
    const float* style       = (const float*)d_in[1];
    const float* noise       = (const float*)d_in[2];
    const float* weight      = (const float*)d_in[3];
    const float* style_w     = (const float*)d_in[4];
    const float* style_b     = (const float*)d_in[5];
    const float* noise_param = (const float*)d_in[6];
    const float* bias_param  = (const float*)d_in[7];
    float* out = (float*)d_out;

    k_style<<<64, 256>>>(style, style_w, style_b);
    k_wmod<<<dim3(CIN, B_), COUT>>>(weight);
    k_sig2<<<64, 256>>>();

    cudaFuncSetAttribute(k_conv, cudaFuncAttributeMaxDynamicSharedMemorySize,
                         SMEM_BYTES);
    k_conv<<<2048, 128, SMEM_BYTES>>>(x, noise, noise_param, bias_param, out);
}

// round 10
// speedup vs baseline: 3.0186x; 1.6574x over previous
#include <cuda_runtime.h>
#include <cuda_fp16.h>
#include <cstdint>

#define B_    4
#define CIN   128
#define COUT  128
#define H_    64
#define W_    64
#define T_    16
#define SS    512
#define NPOS  (H_ * W_ * T_)
#define NCP   (CIN / 2)     // 64 ci-pairs

// ---- static device scratch (no cudaMalloc allowed) ----
__device__ float    g_s[B_ * CIN];
__device__ float    g_w2[COUT * CIN];
__device__ float    g_siginv[B_ * COUT];
__device__ uint32_t g_wth[(size_t)B_ * 9 * NCP * COUT];  // [b][tap][cipair][cout], fp16x2(w*s)
__device__ uint32_t g_xh[(size_t)B_ * NCP * NPOS];       // [b][cipair][pos], fp16x2(x)

__device__ __forceinline__ uint32_t packh2(float lo, float hi) {
    __half2 h = __floats2half2_rn(lo, hi);   // .x = lo (low 16b), .y = hi
    uint32_t u;
    memcpy(&u, &h, 4);
    return u;
}

__device__ __forceinline__ uint32_t smem_u32(const void* p) {
    uint32_t a;
    asm("{ .reg .u64 t; cvta.to.shared.u64 t, %1; cvt.u32.u64 %0, t; }" : "=r"(a) : "l"(p));
    return a;
}

__device__ __forceinline__ void cp16(uint32_t dst, const void* src) {
    asm volatile("cp.async.cg.shared.global [%0], [%1], 16;"
                 :: "r"(dst), "l"(src) : "memory");
}
__device__ __forceinline__ void cp16p(uint32_t dst, const void* src, int ok) {
    asm volatile("cp.async.cg.shared.global [%0], [%1], 16, %2;"
                 :: "r"(dst), "l"(src), "r"(ok ? 16 : 0) : "memory");
}

// ---------------------------------------------------------------------------
// Prologue kernels
// ---------------------------------------------------------------------------
__global__ void k_style(const float* __restrict__ style,
                        const float* __restrict__ style_w,
                        const float* __restrict__ style_b) {
    int wg = blockIdx.x * 8 + (threadIdx.x >> 5);
    int lane = threadIdx.x & 31;
    int b = wg >> 7, i = wg & 127;
    const float* st = style + (size_t)b * SS;
    const float* sw = style_w + (size_t)i * SS;
    float acc = 0.f;
#pragma unroll
    for (int r = 0; r < 16; ++r) acc += st[lane + 32 * r] * sw[lane + 32 * r];
#pragma unroll
    for (int o = 16; o; o >>= 1) acc += __shfl_xor_sync(~0u, acc, o);
    if (lane == 0) g_s[b * CIN + i] = acc + style_b[i];
}

// g_wth[b][tap][cp][cout] = fp16x2(w[o][2cp][tap]*s[b][2cp], w[o][2cp+1][tap]*s[b][2cp+1])
__global__ void k_wmod(const float* __restrict__ weight) {
    int cp = blockIdx.x;          // 0..63
    int b  = blockIdx.y;
    int o  = threadIdx.x;         // 0..127
    float s0 = g_s[b * CIN + 2 * cp];
    float s1 = g_s[b * CIN + 2 * cp + 1];
    const float* w0p = weight + ((size_t)o * CIN + 2 * cp) * 9;
    const float* w1p = w0p + 9;
    float wsq0 = 0.f, wsq1 = 0.f;
#pragma unroll
    for (int tap = 0; tap < 9; ++tap) {
        float w0 = w0p[tap], w1 = w1p[tap];
        wsq0 += w0 * w0;
        wsq1 += w1 * w1;
        g_wth[(((size_t)b * 9 + tap) * NCP + cp) * COUT + o] = packh2(w0 * s0, w1 * s1);
    }
    if (b == 0) {
        g_w2[o * CIN + 2 * cp]     = wsq0;
        g_w2[o * CIN + 2 * cp + 1] = wsq1;
    }
}

__global__ void k_sig2() {
    int wg = blockIdx.x * 8 + (threadIdx.x >> 5);
    int lane = threadIdx.x & 31;
    int b = wg >> 7, o = wg & 127;
    float acc = 0.f;
#pragma unroll
    for (int r = 0; r < 4; ++r) {
        int i = lane + 32 * r;
        float s = g_s[b * CIN + i];
        acc += g_w2[o * CIN + i] * s * s;
    }
#pragma unroll
    for (int off = 16; off; off >>= 1) acc += __shfl_xor_sync(~0u, acc, off);
    if (lane == 0) g_siginv[b * COUT + o] = rsqrtf(acc + 1e-8f);
}

// pack x -> g_xh: word(b, cp, pos) = fp16x2(x[b][2cp][pos], x[b][2cp+1][pos])
// thread handles 4 consecutive pos. total threads = B_*NCP*NPOS/4 = 4.19M.
__global__ void k_xpack(const float* __restrict__ x) {
    unsigned gt = blockIdx.x * 256 + threadIdx.x;
    unsigned pos4 = gt & (NPOS / 4 - 1);        // NPOS/4 = 16384
    unsigned bc   = gt >> 14;                   // b*64 + cp
    unsigned cp   = bc & 63;
    unsigned b    = bc >> 6;
    const float4 v0 = *reinterpret_cast<const float4*>(
        x + ((size_t)(b * CIN + 2 * cp) * NPOS) + pos4 * 4);
    const float4 v1 = *reinterpret_cast<const float4*>(
        x + ((size_t)(b * CIN + 2 * cp + 1) * NPOS) + pos4 * 4);
    uint4 o;
    o.x = packh2(v0.x, v1.x);
    o.y = packh2(v0.y, v1.y);
    o.z = packh2(v0.z, v1.z);
    o.w = packh2(v0.w, v1.w);
    *reinterpret_cast<uint4*>(g_xh + (size_t)bc * NPOS + pos4 * 4) = o;
}

// ---------------------------------------------------------------------------
// Main conv: implicit GEMM, fp16 mma.sync m16n8k16 (f32 accum), cp.async
// double-buffered. CTA 128 thr = 4 warps (2M x 2N), warp tile 64x64.
// CTA tile M=128 x N=128 (8 w x 16 t at fixed b,h). 8 ci-chunks of 16
// (stored as 8 ci-pair rows of fp16x2 words).
// ---------------------------------------------------------------------------
#define SA_STRIDE 136                        // u32 units; mod 32 = 8 -> conflict-free
#define SX_STRIDE 488                        // u32 units; 480 + 8 pad
#define SA_WORDS (72 * SA_STRIDE)            // 9792  (72 rows = 9 taps x 8 kpairs)
#define SX_WORDS (8 * SX_STRIDE)             // 3904  (8 cipair rows)
#define STAGE_WORDS (SA_WORDS + SX_WORDS)    // 13696
#define SMEM_BYTES (2 * STAGE_WORDS * 4)     // 109568

__global__ void __launch_bounds__(128)
k_conv(const float* __restrict__ noise,
       const float* __restrict__ noise_param,
       const float* __restrict__ bias_param,
       float* __restrict__ out) {
    extern __shared__ uint32_t smem[];
    const uint32_t sb = smem_u32(smem);

    const int tid  = threadIdx.x;
    const int lane = tid & 31;
    const int wid  = tid >> 5;
    const int g    = lane >> 2;
    const int q    = lane & 3;
    const int mwarp = (wid >> 1) * 64;
    const int nwarp = (wid & 1) * 64;

    const int bid = blockIdx.x;
    const int b  = bid >> 9;
    const int h  = (bid >> 3) & 63;
    const int w0 = (bid & 7) * 8;

    float acc[4][8][4];
#pragma unroll
    for (int mf = 0; mf < 4; ++mf)
#pragma unroll
        for (int nf = 0; nf < 8; ++nf)
#pragma unroll
            for (int r = 0; r < 4; ++r) acc[mf][nf][r] = 0.f;

    // ---- stage chunk c (16 ci = 8 cipairs): A and X via cp.async ----
    auto stage_load = [&](int c, int s) {
        const int cp0 = c * 8;
        const uint32_t sa = sb + (uint32_t)(s * STAGE_WORDS) * 4;
        const uint32_t sx = sa + SA_WORDS * 4;
        // A: 72 rows (tap*8+kp) x 128 couts u32 = 2304 x 16B, 18/thread
#pragma unroll
        for (int i = 0; i < 18; ++i) {
            int li  = tid + i * 128;
            int row = li >> 5;
            int seg = li & 31;
            int tap = row >> 3, kp = row & 7;
            const uint32_t* src = g_wth +
                (((size_t)(b * 9 + tap) * NCP) + cp0 + kp) * COUT + seg * 4;
            cp16(sa + (uint32_t)(row * SA_STRIDE + seg * 4) * 4, src);
        }
        // X: 8 cipairs x 30 pos x 4 segs = 960 x 16B (zfill OOB)
        for (int li = tid; li < 960; li += 128) {
            int cp  = li / 120;
            int r   = li - cp * 120;
            int pos = r >> 2;
            int t4  = (r & 3) << 2;
            int dh  = pos / 10;
            int wl  = pos - dh * 10;
            int gh  = h + dh - 1;
            int gw  = w0 + wl - 1;
            int ok  = ((unsigned)gh < (unsigned)H_) & ((unsigned)gw < (unsigned)W_);
            int ghc = ok ? gh : 0;
            int gwc = ok ? gw : 0;
            const uint32_t* src = g_xh +
                ((size_t)(b * NCP) + cp0 + cp) * NPOS + ((ghc * W_ + gwc) * T_ + t4);
            cp16p(sx + (uint32_t)(cp * SX_STRIDE + pos * 16 + t4) * 4, src, ok);
        }
    };

    auto compute = [&](int s) {
        const uint32_t* sA = smem + s * STAGE_WORDS;
        const uint32_t* sX = sA + SA_WORDS;
#pragma unroll
        for (int kh = 0; kh < 3; ++kh) {
            // 12 shared B-frag pairs cover all 3 kw shifts
            uint32_t b0[12], b1[12];
            const uint32_t* bp = sX + q * SX_STRIDE + kh * 160 + nwarp + g;
#pragma unroll
            for (int f = 0; f < 12; ++f) {
                b0[f] = bp[f * 8];
                b1[f] = bp[f * 8 + 4 * SX_STRIDE];
            }
#pragma unroll
            for (int kw = 0; kw < 3; ++kw) {
                const int t8 = (kh * 3 + kw) * 8;
                uint32_t a[4][4];
                const uint32_t* ap = sA + (t8 + q) * SA_STRIDE + mwarp + g;
#pragma unroll
                for (int mf = 0; mf < 4; ++mf) {
                    const uint32_t* p = ap + mf * 16;
                    a[mf][0] = p[0];
                    a[mf][1] = p[8];
                    a[mf][2] = p[4 * SA_STRIDE];
                    a[mf][3] = p[4 * SA_STRIDE + 8];
                }
#pragma unroll
                for (int mf = 0; mf < 4; ++mf) {
#pragma unroll
                    for (int nf = 0; nf < 8; ++nf) {
                        const int f = kw * 2 + nf;
                        asm volatile(
                            "mma.sync.aligned.m16n8k16.row.col.f32.f16.f16.f32 "
                            "{%0,%1,%2,%3}, {%4,%5,%6,%7}, {%8,%9}, {%0,%1,%2,%3};"
                            : "+f"(acc[mf][nf][0]), "+f"(acc[mf][nf][1]),
                              "+f"(acc[mf][nf][2]), "+f"(acc[mf][nf][3])
                            : "r"(a[mf][0]), "r"(a[mf][1]), "r"(a[mf][2]), "r"(a[mf][3]),
                              "r"(b0[f]), "r"(b1[f]));
                    }
                }
            }
        }
    };

    // ---- pipelined mainloop: 8 chunks of 16 ci ----
    stage_load(0, 0);
    asm volatile("cp.async.commit_group;" ::: "memory");
#pragma unroll 1
    for (int c = 0; c < 8; ++c) {
        if (c < 7) {
            stage_load(c + 1, (c + 1) & 1);
            asm volatile("cp.async.commit_group;" ::: "memory");
            asm volatile("cp.async.wait_group 1;" ::: "memory");
        } else {
            asm volatile("cp.async.wait_group 0;" ::: "memory");
        }
        __syncthreads();
        compute(c & 1);
        __syncthreads();
    }

    // ---- epilogue: demodulate + noise + bias ----
    float si[4][2], np[4][2], bp2[4][2];
#pragma unroll
    for (int mf = 0; mf < 4; ++mf)
#pragma unroll
        for (int hf = 0; hf < 2; ++hf) {
            int m = mwarp + mf * 16 + g + hf * 8;
            si[mf][hf]  = g_siginv[b * COUT + m];
            np[mf][hf]  = noise_param[m];
            bp2[mf][hf] = bias_param[m];
        }
#pragma unroll
    for (int nf = 0; nf < 8; ++nf) {
        int n  = nwarp + nf * 8 + q * 2;
        int wl = n >> 4;
        int t  = n & 15;
        float2 nz = *reinterpret_cast<const float2*>(
            noise + (((size_t)b * H_ + h) * W_ + w0 + wl) * T_ + t);
#pragma unroll
        for (int mf = 0; mf < 4; ++mf) {
#pragma unroll
            for (int hf = 0; hf < 2; ++hf) {
                int m = mwarp + mf * 16 + g + hf * 8;
                float2 r;
                r.x = acc[mf][nf][hf * 2 + 0] * si[mf][hf] + np[mf][hf] * nz.x + bp2[mf][hf];
                r.y = acc[mf][nf][hf * 2 + 1] * si[mf][hf] + np[mf][hf] * nz.y + bp2[mf][hf];
                *reinterpret_cast<float2*>(
                    out + ((((size_t)b * COUT + m) * H_ + h) * W_ + w0 + wl) * T_ + t) = r;
            }
        }
    }
}

// ---------------------------------------------------------------------------
// Launch. inputs: x, style, noise, weight, style_w, style_b, noise_param,
//                 bias_param
// ---------------------------------------------------------------------------
extern "C" void kernel_launch(void* const* d_in, const int* in_sizes, int n_in,
                              void* d_out, int out_size) {
    const float* x           = (const float*)d_in[0];
    const float* style       = (const float*)d_in[1];
    const float* noise       = (const float*)d_in[2];
    const float* weight      = (const float*)d_in[3];
    const float* style_w     = (const float*)d_in[4];
    const float* style_b     = (const float*)d_in[5];
    const float* noise_param = (const float*)d_in[6];
    const float* bias_param  = (const float*)d_in[7];
    float* out = (float*)d_out;

    k_style<<<64, 256>>>(style, style_w, style_b);
    k_wmod<<<dim3(NCP, B_), COUT>>>(weight);
    k_sig2<<<64, 256>>>();
    // B_*NCP*NPOS/4 threads = 4.19M -> 16384 blocks x 256
    k_xpack<<<16384, 256>>>(x);

    cudaFuncSetAttribute(k_conv, cudaFuncAttributeMaxDynamicSharedMemorySize,
                         SMEM_BYTES);
    k_conv<<<2048, 128, SMEM_BYTES>>>(noise, noise_param, bias_param, out);
}

// round 12
// speedup vs baseline: 3.1493x; 1.0433x over previous
#include <cuda_runtime.h>
#include <cuda_fp16.h>
#include <cstdint>

#define B_    4
#define CIN   128
#define COUT  128
#define H_    64
#define W_    64
#define T_    16
#define SS    512
#define NPOS  (H_ * W_ * T_)
#define NCP   (CIN / 2)     // 64 ci-pairs

// ---- static device scratch (no cudaMalloc allowed) ----
__device__ float    g_s[B_ * CIN];
__device__ float    g_w2[COUT * CIN];
__device__ float    g_siginv[B_ * COUT];
__device__ uint32_t g_wth[(size_t)B_ * 9 * NCP * COUT];  // [b][tap][cipair][cout], fp16x2(w*s)
__device__ uint32_t g_xh[(size_t)B_ * NCP * NPOS];       // [b][cipair][pos], fp16x2(x)

__device__ __forceinline__ uint32_t packh2(float lo, float hi) {
    __half2 h = __floats2half2_rn(lo, hi);
    uint32_t u;
    memcpy(&u, &h, 4);
    return u;
}

__device__ __forceinline__ uint32_t smem_u32(const void* p) {
    uint32_t a;
    asm("{ .reg .u64 t; cvta.to.shared.u64 t, %1; cvt.u32.u64 %0, t; }" : "=r"(a) : "l"(p));
    return a;
}

__device__ __forceinline__ void cp16(uint32_t dst, const void* src) {
    asm volatile("cp.async.cg.shared.global [%0], [%1], 16;"
                 :: "r"(dst), "l"(src) : "memory");
}
__device__ __forceinline__ void cp16p(uint32_t dst, const void* src, int ok) {
    asm volatile("cp.async.cg.shared.global [%0], [%1], 16, %2;"
                 :: "r"(dst), "l"(src), "r"(ok ? 16 : 0) : "memory");
}

// ---- mbarrier helpers ----
#define MBAR_INIT(a, n) \
    asm volatile("mbarrier.init.shared.b64 [%0], %1;" :: "r"(a), "r"(n) : "memory")
#define MBAR_ARRIVE(a) \
    asm volatile("mbarrier.arrive.shared.b64 _, [%0];" :: "r"(a) : "memory")
// .noinc: the async-completion itself counts toward the init arrival count.
#define CPASYNC_MBAR_ARRIVE(a) \
    asm volatile("cp.async.mbarrier.arrive.noinc.shared.b64 [%0];" :: "r"(a) : "memory")

__device__ __forceinline__ void mbar_wait(uint32_t mbar, uint32_t parity) {
    asm volatile(
        "{\n\t.reg .pred P;\n\t"
        "WL_%=:\n\t"
        "mbarrier.try_wait.parity.acquire.cta.shared::cta.b64 P, [%0], %1, 0x989680;\n\t"
        "@P bra.uni WD_%=;\n\t"
        "bra.uni WL_%=;\n\t"
        "WD_%=:\n\t}"
        :: "r"(mbar), "r"(parity) : "memory");
}

// ---------------------------------------------------------------------------
// Prologue kernels
// ---------------------------------------------------------------------------
__global__ void k_style(const float* __restrict__ style,
                        const float* __restrict__ style_w,
                        const float* __restrict__ style_b) {
    int wg = blockIdx.x * 8 + (threadIdx.x >> 5);
    int lane = threadIdx.x & 31;
    int b = wg >> 7, i = wg & 127;
    const float* st = style + (size_t)b * SS;
    const float* sw = style_w + (size_t)i * SS;
    float acc = 0.f;
#pragma unroll
    for (int r = 0; r < 16; ++r) acc += st[lane + 32 * r] * sw[lane + 32 * r];
#pragma unroll
    for (int o = 16; o; o >>= 1) acc += __shfl_xor_sync(~0u, acc, o);
    if (lane == 0) g_s[b * CIN + i] = acc + style_b[i];
}

// g_wth[b][tap][cp][cout] = fp16x2(w[o][2cp][tap]*s[b][2cp], w[o][2cp+1][tap]*s[b][2cp+1])
__global__ void k_wmod(const float* __restrict__ weight) {
    int cp = blockIdx.x;          // 0..63
    int b  = blockIdx.y;
    int o  = threadIdx.x;         // 0..127
    float s0 = g_s[b * CIN + 2 * cp];
    float s1 = g_s[b * CIN + 2 * cp + 1];
    const float* w0p = weight + ((size_t)o * CIN + 2 * cp) * 9;
    const float* w1p = w0p + 9;
    float wsq0 = 0.f, wsq1 = 0.f;
#pragma unroll
    for (int tap = 0; tap < 9; ++tap) {
        float w0 = w0p[tap], w1 = w1p[tap];
        wsq0 += w0 * w0;
        wsq1 += w1 * w1;
        g_wth[(((size_t)b * 9 + tap) * NCP + cp) * COUT + o] = packh2(w0 * s0, w1 * s1);
    }
    if (b == 0) {
        g_w2[o * CIN + 2 * cp]     = wsq0;
        g_w2[o * CIN + 2 * cp + 1] = wsq1;
    }
}

__global__ void k_sig2() {
    int wg = blockIdx.x * 8 + (threadIdx.x >> 5);
    int lane = threadIdx.x & 31;
    int b = wg >> 7, o = wg & 127;
    float acc = 0.f;
#pragma unroll
    for (int r = 0; r < 4; ++r) {
        int i = lane + 32 * r;
        float s = g_s[b * CIN + i];
        acc += g_w2[o * CIN + i] * s * s;
    }
#pragma unroll
    for (int off = 16; off; off >>= 1) acc += __shfl_xor_sync(~0u, acc, off);
    if (lane == 0) g_siginv[b * COUT + o] = rsqrtf(acc + 1e-8f);
}

// pack x -> g_xh: word(b, cp, pos) = fp16x2(x[b][2cp][pos], x[b][2cp+1][pos])
__global__ void k_xpack(const float* __restrict__ x) {
    unsigned gt = blockIdx.x * 256 + threadIdx.x;
    unsigned pos4 = gt & (NPOS / 4 - 1);
    unsigned bc   = gt >> 14;
    unsigned cp   = bc & 63;
    unsigned b    = bc >> 6;
    const float4 v0 = *reinterpret_cast<const float4*>(
        x + ((size_t)(b * CIN + 2 * cp) * NPOS) + pos4 * 4);
    const float4 v1 = *reinterpret_cast<const float4*>(
        x + ((size_t)(b * CIN + 2 * cp + 1) * NPOS) + pos4 * 4);
    uint4 o;
    o.x = packh2(v0.x, v1.x);
    o.y = packh2(v0.y, v1.y);
    o.z = packh2(v0.z, v1.z);
    o.w = packh2(v0.w, v1.w);
    *reinterpret_cast<uint4*>(g_xh + (size_t)bc * NPOS + pos4 * 4) = o;
}

// ---------------------------------------------------------------------------
// Main conv: implicit GEMM, fp16 mma.sync m16n8k16 (f32 accum), cp.async
// double-buffered with mbarrier full/empty handshake (no __syncthreads in
// the mainloop). CTA 128 thr = 4 warps (2M x 2N), warp tile 64x64.
// CTA tile M=128 x N=128. 8 ci-chunks of 16 (8 ci-pair rows of fp16x2).
// ---------------------------------------------------------------------------
#define SA_STRIDE 136
#define SX_STRIDE 488
#define SA_WORDS (72 * SA_STRIDE)            // 9792
#define SX_WORDS (8 * SX_STRIDE)             // 3904
#define STAGE_WORDS (SA_WORDS + SX_WORDS)    // 13696
#define MB_BYTES 64
#define SMEM_BYTES (2 * STAGE_WORDS * 4 + MB_BYTES)   // 109632

__global__ void __launch_bounds__(128)
k_conv(const float* __restrict__ noise,
       const float* __restrict__ noise_param,
       const float* __restrict__ bias_param,
       float* __restrict__ out) {
    extern __shared__ uint32_t smem[];
    const uint32_t sb = smem_u32(smem);
    const uint32_t mb_full0  = sb + 2 * STAGE_WORDS * 4;
    const uint32_t mb_full1  = mb_full0 + 8;
    const uint32_t mb_empty0 = mb_full0 + 16;
    const uint32_t mb_empty1 = mb_full0 + 24;

    const int tid  = threadIdx.x;
    const int lane = tid & 31;
    const int wid  = tid >> 5;
    const int g    = lane >> 2;
    const int q    = lane & 3;
    const int mwarp = (wid >> 1) * 64;
    const int nwarp = (wid & 1) * 64;

    const int bid = blockIdx.x;
    const int b  = bid >> 9;
    const int h  = (bid >> 3) & 63;
    const int w0 = (bid & 7) * 8;

    if (tid == 0) {
        MBAR_INIT(mb_full0, 128);
        MBAR_INIT(mb_full1, 128);
        MBAR_INIT(mb_empty0, 128);
        MBAR_INIT(mb_empty1, 128);
    }
    __syncthreads();   // mbarrier init visibility (once, outside mainloop)

    float acc[4][8][4];
#pragma unroll
    for (int mf = 0; mf < 4; ++mf)
#pragma unroll
        for (int nf = 0; nf < 8; ++nf)
#pragma unroll
            for (int r = 0; r < 4; ++r) acc[mf][nf][r] = 0.f;

    // ---- stage chunk c (16 ci = 8 cipairs): A and X via cp.async ----
    auto stage_load = [&](int c, int s) {
        const int cp0 = c * 8;
        const uint32_t sa = sb + (uint32_t)(s * STAGE_WORDS) * 4;
        const uint32_t sx = sa + SA_WORDS * 4;
#pragma unroll
        for (int i = 0; i < 18; ++i) {
            int li  = tid + i * 128;
            int row = li >> 5;
            int seg = li & 31;
            int tap = row >> 3, kp = row & 7;
            const uint32_t* src = g_wth +
                (((size_t)(b * 9 + tap) * NCP) + cp0 + kp) * COUT + seg * 4;
            cp16(sa + (uint32_t)(row * SA_STRIDE + seg * 4) * 4, src);
        }
        for (int li = tid; li < 960; li += 128) {
            int cp  = li / 120;
            int r   = li - cp * 120;
            int pos = r >> 2;
            int t4  = (r & 3) << 2;
            int dh  = pos / 10;
            int wl  = pos - dh * 10;
            int gh  = h + dh - 1;
            int gw  = w0 + wl - 1;
            int ok  = ((unsigned)gh < (unsigned)H_) & ((unsigned)gw < (unsigned)W_);
            int ghc = ok ? gh : 0;
            int gwc = ok ? gw : 0;
            const uint32_t* src = g_xh +
                ((size_t)(b * NCP) + cp0 + cp) * NPOS + ((ghc * W_ + gwc) * T_ + t4);
            cp16p(sx + (uint32_t)(cp * SX_STRIDE + pos * 16 + t4) * 4, src, ok);
        }
    };

    auto compute = [&](int s) {
        const uint32_t* sA = smem + s * STAGE_WORDS;
        const uint32_t* sX = sA + SA_WORDS;
#pragma unroll
        for (int kh = 0; kh < 3; ++kh) {
            uint32_t b0[12], b1[12];
            const uint32_t* bp = sX + q * SX_STRIDE + kh * 160 + nwarp + g;
#pragma unroll
            for (int f = 0; f < 12; ++f) {
                b0[f] = bp[f * 8];
                b1[f] = bp[f * 8 + 4 * SX_STRIDE];
            }
#pragma unroll
            for (int kw = 0; kw < 3; ++kw) {
                const int t8 = (kh * 3 + kw) * 8;
                uint32_t a[4][4];
                const uint32_t* ap = sA + (t8 + q) * SA_STRIDE + mwarp + g;
#pragma unroll
                for (int mf = 0; mf < 4; ++mf) {
                    const uint32_t* p = ap + mf * 16;
                    a[mf][0] = p[0];
                    a[mf][1] = p[8];
                    a[mf][2] = p[4 * SA_STRIDE];
                    a[mf][3] = p[4 * SA_STRIDE + 8];
                }
#pragma unroll
                for (int mf = 0; mf < 4; ++mf) {
#pragma unroll
                    for (int nf = 0; nf < 8; ++nf) {
                        const int f = kw * 2 + nf;
                        asm volatile(
                            "mma.sync.aligned.m16n8k16.row.col.f32.f16.f16.f32 "
                            "{%0,%1,%2,%3}, {%4,%5,%6,%7}, {%8,%9}, {%0,%1,%2,%3};"
                            : "+f"(acc[mf][nf][0]), "+f"(acc[mf][nf][1]),
                              "+f"(acc[mf][nf][2]), "+f"(acc[mf][nf][3])
                            : "r"(a[mf][0]), "r"(a[mf][1]), "r"(a[mf][2]), "r"(a[mf][3]),
                              "r"(b0[f]), "r"(b1[f]));
                    }
                }
            }
        }
    };

    // ---- mbarrier-handshook double-buffered mainloop (8 chunks) ----
    stage_load(0, 0);
    CPASYNC_MBAR_ARRIVE(mb_full0);
    stage_load(1, 1);
    CPASYNC_MBAR_ARRIVE(mb_full1);

#pragma unroll 1
    for (int c = 0; c < 8; ++c) {
        const int s = c & 1;
        const uint32_t fullb  = s ? mb_full1 : mb_full0;
        const uint32_t emptyb = s ? mb_empty1 : mb_empty0;
        const uint32_t par = (c >> 1) & 1;

        mbar_wait(fullb, par);      // data-driven: no warp rendezvous
        compute(s);
        MBAR_ARRIVE(emptyb);        // this warp done reading buffer s
        if (c + 2 < 8) {
            mbar_wait(emptyb, par); // all warps done with buffer s
            stage_load(c + 2, s);
            CPASYNC_MBAR_ARRIVE(fullb);
        }
    }

    // ---- epilogue: demodulate + noise + bias ----
    float si[4][2], np[4][2], bp2[4][2];
#pragma unroll
    for (int mf = 0; mf < 4; ++mf)
#pragma unroll
        for (int hf = 0; hf < 2; ++hf) {
            int m = mwarp + mf * 16 + g + hf * 8;
            si[mf][hf]  = g_siginv[b * COUT + m];
            np[mf][hf]  = noise_param[m];
            bp2[mf][hf] = bias_param[m];
        }
#pragma unroll
    for (int nf = 0; nf < 8; ++nf) {
        int n  = nwarp + nf * 8 + q * 2;
        int wl = n >> 4;
        int t  = n & 15;
        float2 nz = *reinterpret_cast<const float2*>(
            noise + (((size_t)b * H_ + h) * W_ + w0 + wl) * T_ + t);
#pragma unroll
        for (int mf = 0; mf < 4; ++mf) {
#pragma unroll
            for (int hf = 0; hf < 2; ++hf) {
                int m = mwarp + mf * 16 + g + hf * 8;
                float2 r;
                r.x = acc[mf][nf][hf * 2 + 0] * si[mf][hf] + np[mf][hf] * nz.x + bp2[mf][hf];
                r.y = acc[mf][nf][hf * 2 + 1] * si[mf][hf] + np[mf][hf] * nz.y + bp2[mf][hf];
                *reinterpret_cast<float2*>(
                    out + ((((size_t)b * COUT + m) * H_ + h) * W_ + w0 + wl) * T_ + t) = r;
            }
        }
    }
}

// ---------------------------------------------------------------------------
// Launch. inputs: x, style, noise, weight, style_w, style_b, noise_param,
//                 bias_param
// ---------------------------------------------------------------------------
extern "C" void kernel_launch(void* const* d_in, const int* in_sizes, int n_in,
                              void* d_out, int out_size) {
    const float* x           = (const float*)d_in[0];
    const float* style       = (const float*)d_in[1];
    const float* noise       = (const float*)d_in[2];
    const float* weight      = (const float*)d_in[3];
    const float* style_w     = (const float*)d_in[4];
    const float* style_b     = (const float*)d_in[5];
    const float* noise_param = (const float*)d_in[6];
    const float* bias_param  = (const float*)d_in[7];
    float* out = (float*)d_out;

    k_style<<<64, 256>>>(style, style_w, style_b);
    k_wmod<<<dim3(NCP, B_), COUT>>>(weight);
    k_sig2<<<64, 256>>>();
    k_xpack<<<16384, 256>>>(x);

    cudaFuncSetAttribute(k_conv, cudaFuncAttributeMaxDynamicSharedMemorySize,
                         SMEM_BYTES);
    k_conv<<<2048, 128, SMEM_BYTES>>>(noise, noise_param, bias_param, out);
}

// round 14
// speedup vs baseline: 3.1824x; 1.0105x over previous
#include <cuda_runtime.h>
#include <cuda_fp16.h>
#include <cstdint>

#define B_    4
#define CIN   128
#define COUT  128
#define H_    64
#define W_    64
#define T_    16
#define SS    512
#define NPOS  (H_ * W_ * T_)

// ---- static device scratch (no cudaMalloc allowed) ----
__device__ float    g_s[B_ * CIN];
__device__ float    g_w2[COUT * CIN];
__device__ float    g_siginv[B_ * COUT];
// A in fragment order: [b][chunk 0..7][tap 0..8][mtile 0..7][lane 0..31] x uint4
__device__ uint4    g_wtf[(size_t)B_ * 8 * 9 * 8 * 32];
// X with k-half pairs adjacent: per (b, chunk, q): NPOS pos x {slot0, slot1}
// = 2*NPOS fp16x2 words = NPOS/2 uint4 units (each unit = 2 pos x 2 slots).
__device__ uint4    g_xq[(size_t)B_ * 8 * 4 * (NPOS / 2)];

__device__ __forceinline__ uint32_t packh2(float lo, float hi) {
    __half2 h = __floats2half2_rn(lo, hi);
    uint32_t u;
    memcpy(&u, &h, 4);
    return u;
}

__device__ __forceinline__ uint32_t smem_u32(const void* p) {
    uint32_t a;
    asm("{ .reg .u64 t; cvta.to.shared.u64 t, %1; cvt.u32.u64 %0, t; }" : "=r"(a) : "l"(p));
    return a;
}

__device__ __forceinline__ void cp16(uint32_t dst, const void* src) {
    asm volatile("cp.async.cg.shared.global [%0], [%1], 16;"
                 :: "r"(dst), "l"(src) : "memory");
}
__device__ __forceinline__ void cp16p(uint32_t dst, const void* src, int ok) {
    asm volatile("cp.async.cg.shared.global [%0], [%1], 16, %2;"
                 :: "r"(dst), "l"(src), "r"(ok ? 16 : 0) : "memory");
}

// ---- mbarrier helpers ----
#define MBAR_INIT(a, n) \
    asm volatile("mbarrier.init.shared.b64 [%0], %1;" :: "r"(a), "r"(n) : "memory")
#define MBAR_ARRIVE(a) \
    asm volatile("mbarrier.arrive.shared.b64 _, [%0];" :: "r"(a) : "memory")
#define CPASYNC_MBAR_ARRIVE(a) \
    asm volatile("cp.async.mbarrier.arrive.noinc.shared.b64 [%0];" :: "r"(a) : "memory")

__device__ __forceinline__ void mbar_wait(uint32_t mbar, uint32_t parity) {
    asm volatile(
        "{\n\t.reg .pred P;\n\t"
        "WL_%=:\n\t"
        "mbarrier.try_wait.parity.acquire.cta.shared::cta.b64 P, [%0], %1, 0x989680;\n\t"
        "@P bra.uni WD_%=;\n\t"
        "bra.uni WL_%=;\n\t"
        "WD_%=:\n\t}"
        :: "r"(mbar), "r"(parity) : "memory");
}

// ---------------------------------------------------------------------------
// Prologue kernels
// ---------------------------------------------------------------------------
__global__ void k_style(const float* __restrict__ style,
                        const float* __restrict__ style_w,
                        const float* __restrict__ style_b) {
    int wg = blockIdx.x * 8 + (threadIdx.x >> 5);
    int lane = threadIdx.x & 31;
    int b = wg >> 7, i = wg & 127;
    const float* st = style + (size_t)b * SS;
    const float* sw = style_w + (size_t)i * SS;
    float acc = 0.f;
#pragma unroll
    for (int r = 0; r < 16; ++r) acc += st[lane + 32 * r] * sw[lane + 32 * r];
#pragma unroll
    for (int o = 16; o; o >>= 1) acc += __shfl_xor_sync(~0u, acc, o);
    if (lane == 0) g_s[b * CIN + i] = acc + style_b[i];
}

// g_w2[o][i] = sum_tap w^2 (style-independent)
__global__ void k_w2(const float* __restrict__ weight) {
    int i = blockIdx.x, o = threadIdx.x;
    const float* wp = weight + ((size_t)o * CIN + i) * 9;
    float wsq = 0.f;
#pragma unroll
    for (int tap = 0; tap < 9; ++tap) { float w = wp[tap]; wsq += w * w; }
    g_w2[o * CIN + i] = wsq;
}

__global__ void k_sig2() {
    int wg = blockIdx.x * 8 + (threadIdx.x >> 5);
    int lane = threadIdx.x & 31;
    int b = wg >> 7, o = wg & 127;
    float acc = 0.f;
#pragma unroll
    for (int r = 0; r < 4; ++r) {
        int i = lane + 32 * r;
        float s = g_s[b * CIN + i];
        acc += g_w2[o * CIN + i] * s * s;
    }
#pragma unroll
    for (int off = 16; off; off >>= 1) acc += __shfl_xor_sync(~0u, acc, off);
    if (lane == 0) g_siginv[b * COUT + o] = rsqrtf(acc + 1e-8f);
}

// Build fragment-ordered modulated weights.
// grid (72, B_) [blockIdx.x = c*9+tap], block 256 [mt = tid>>5, lane = tid&31]
__global__ void k_wfrag(const float* __restrict__ weight) {
    int c   = blockIdx.x / 9;
    int tap = blockIdx.x - c * 9;
    int b   = blockIdx.y;
    int tid = threadIdx.x;
    int lane = tid & 31, mt = tid >> 5;
    int q = lane & 3, g = lane >> 2;

    int cout1 = mt * 16 + g;
    int cout2 = cout1 + 8;
    int ciA = c * 16 + 2 * q;        // kp = q
    int ciB = ciA + 8;               // kp = q + 4

    float sA0 = g_s[b * CIN + ciA],     sA1 = g_s[b * CIN + ciA + 1];
    float sB0 = g_s[b * CIN + ciB],     sB1 = g_s[b * CIN + ciB + 1];

    const float* w = weight;
    uint4 o;
    o.x = packh2(w[((size_t)cout1 * CIN + ciA) * 9 + tap] * sA0,
                 w[((size_t)cout1 * CIN + ciA + 1) * 9 + tap] * sA1);
    o.y = packh2(w[((size_t)cout2 * CIN + ciA) * 9 + tap] * sA0,
                 w[((size_t)cout2 * CIN + ciA + 1) * 9 + tap] * sA1);
    o.z = packh2(w[((size_t)cout1 * CIN + ciB) * 9 + tap] * sB0,
                 w[((size_t)cout1 * CIN + ciB + 1) * 9 + tap] * sB1);
    o.w = packh2(w[((size_t)cout2 * CIN + ciB) * 9 + tap] * sB0,
                 w[((size_t)cout2 * CIN + ciB + 1) * 9 + tap] * sB1);
    g_wtf[(((size_t)(b * 8 + c) * 72) + tap * 8 + mt) * 32 + lane] = o;
}

// Pack x -> g_xq. Unit (b,c,q,pos-pair): {slot0@p0, slot1@p0, slot0@p1, slot1@p1}
// slot0 = fp16x2(ci = 16c+2q, +1), slot1 = fp16x2(ci = 16c+2q+8, +9).
// Each thread does 4 pos (2 uint4 units).
__global__ void k_xpack(const float* __restrict__ x) {
    unsigned gt = blockIdx.x * 256 + threadIdx.x;
    unsigned pos4 = gt & (NPOS / 4 - 1);        // 16384 positions-of-4
    unsigned idx  = gt >> 14;                   // b*32 + c*4 + q
    unsigned q = idx & 3;
    unsigned c = (idx >> 2) & 7;
    unsigned b = idx >> 5;
    unsigned r0 = 16 * c + 2 * q;

    const float4 v00 = *reinterpret_cast<const float4*>(
        x + (size_t)(b * CIN + r0)     * NPOS + pos4 * 4);
    const float4 v01 = *reinterpret_cast<const float4*>(
        x + (size_t)(b * CIN + r0 + 1) * NPOS + pos4 * 4);
    const float4 v10 = *reinterpret_cast<const float4*>(
        x + (size_t)(b * CIN + r0 + 8) * NPOS + pos4 * 4);
    const float4 v11 = *reinterpret_cast<const float4*>(
        x + (size_t)(b * CIN + r0 + 9) * NPOS + pos4 * 4);

    uint4 u0, u1;
    u0.x = packh2(v00.x, v01.x); u0.y = packh2(v10.x, v11.x);
    u0.z = packh2(v00.y, v01.y); u0.w = packh2(v10.y, v11.y);
    u1.x = packh2(v00.z, v01.z); u1.y = packh2(v10.z, v11.z);
    u1.z = packh2(v00.w, v01.w); u1.w = packh2(v10.w, v11.w);

    uint4* dst = g_xq + (size_t)idx * (NPOS / 2) + pos4 * 2;
    dst[0] = u0;
    dst[1] = u1;
}

// ---------------------------------------------------------------------------
// Main conv: implicit GEMM, fp16 mma.sync m16n8k16 (f32 accum), cp.async
// double-buffered with mbarrier full/empty handshake.
// CTA 128 thr = 4 warps (2M x 2N), warp tile 64x64, CTA tile 128x128.
// 8 ci-chunks of 16. A frags via LDS.128, B frag pairs via LDS.64.
// ---------------------------------------------------------------------------
#define SA_WORDS 9216                        // 72 frag-rows x 32 lanes x 4 words
#define SXP      968                         // per-q row stride (960 + 8 pad)
#define SX_WORDS (4 * SXP)                   // 3872
#define STAGE_WORDS (SA_WORDS + SX_WORDS)    // 13088
#define MB_BYTES 64
#define SMEM_BYTES (2 * STAGE_WORDS * 4 + MB_BYTES)   // 104768

__global__ void __launch_bounds__(128)
k_conv(const float* __restrict__ noise,
       const float* __restrict__ noise_param,
       const float* __restrict__ bias_param,
       float* __restrict__ out) {
    extern __shared__ uint32_t smem[];
    const uint32_t sb = smem_u32(smem);
    const uint32_t mb_full0  = sb + 2 * STAGE_WORDS * 4;
    const uint32_t mb_full1  = mb_full0 + 8;
    const uint32_t mb_empty0 = mb_full0 + 16;
    const uint32_t mb_empty1 = mb_full0 + 24;

    const int tid  = threadIdx.x;
    const int lane = tid & 31;
    const int wid  = tid >> 5;
    const int g    = lane >> 2;
    const int q    = lane & 3;
    const int mwarp = (wid >> 1) * 64;
    const int nwarp = (wid & 1) * 64;
    const int mt0   = (wid >> 1) * 4;         // base mtile for this warp

    const int bid = blockIdx.x;
    const int b  = bid >> 9;
    const int h  = (bid >> 3) & 63;
    const int w0 = (bid & 7) * 8;

    if (tid == 0) {
        MBAR_INIT(mb_full0, 128);
        MBAR_INIT(mb_full1, 128);
        MBAR_INIT(mb_empty0, 128);
        MBAR_INIT(mb_empty1, 128);
    }
    __syncthreads();

    float acc[4][8][4];
#pragma unroll
    for (int mf = 0; mf < 4; ++mf)
#pragma unroll
        for (int nf = 0; nf < 8; ++nf)
#pragma unroll
            for (int r = 0; r < 4; ++r) acc[mf][nf][r] = 0.f;

    // ---- stage chunk c into buffer s ----
    auto stage_load = [&](int c, int s) {
        const uint32_t sa = sb + (uint32_t)(s * STAGE_WORDS) * 4;
        const uint32_t sx = sa + SA_WORDS * 4;
        // A: flat copy of 2304 x 16B fragment units
        const uint4* asrc = g_wtf + (size_t)(b * 8 + c) * 2304;
#pragma unroll
        for (int i = 0; i < 18; ++i) {
            int li = tid + i * 128;
            cp16(sa + (uint32_t)li * 16, asrc + li);
        }
        // X: 4 q-rows x 240 pos-pair units (3dh x 10wl x 8 t2)
        const uint4* xbase = g_xq + (size_t)(b * 32 + c * 4) * (NPOS / 2);
        for (int li = tid; li < 960; li += 128) {
            int qq = li / 240;
            int r  = li - qq * 240;
            int dh = r / 80;
            int rr = r - dh * 80;
            int wl = rr >> 3;
            int t2 = rr & 7;
            int gh = h + dh - 1;
            int gw = w0 + wl - 1;
            int ok = ((unsigned)gh < (unsigned)H_) & ((unsigned)gw < (unsigned)W_);
            int ghc = ok ? gh : 0;
            int gwc = ok ? gw : 0;
            const uint4* src = xbase + (size_t)qq * (NPOS / 2)
                               + (ghc * W_ + gwc) * 8 + t2;
            uint32_t dst = sx + (uint32_t)(qq * SXP + 32 * (dh * 10 + wl) + 4 * t2) * 4;
            cp16p(dst, src, ok);
        }
    };

    auto compute = [&](int s) {
        const uint32_t* sA = smem + s * STAGE_WORDS;
        const uint4* sa4 = reinterpret_cast<const uint4*>(sA);
        const uint2* sx2 = reinterpret_cast<const uint2*>(sA + SA_WORDS);
#pragma unroll
        for (int kh = 0; kh < 3; ++kh) {
            // 12 B-frag pairs (LDS.64) cover all 3 kw shifts
            uint32_t b0[12], b1[12];
            const uint2* bp = sx2 + q * (SXP / 2) + kh * 160 + nwarp + g;
#pragma unroll
            for (int f = 0; f < 12; ++f) {
                uint2 bv = bp[f * 8];
                b0[f] = bv.x;
                b1[f] = bv.y;
            }
#pragma unroll
            for (int kw = 0; kw < 3; ++kw) {
                const int tap = kh * 3 + kw;
                uint4 a[4];
#pragma unroll
                for (int mf = 0; mf < 4; ++mf)
                    a[mf] = sa4[(tap * 8 + mt0 + mf) * 32 + lane];
#pragma unroll
                for (int mf = 0; mf < 4; ++mf) {
#pragma unroll
                    for (int nf = 0; nf < 8; ++nf) {
                        const int f = kw * 2 + nf;
                        asm volatile(
                            "mma.sync.aligned.m16n8k16.row.col.f32.f16.f16.f32 "
                            "{%0,%1,%2,%3}, {%4,%5,%6,%7}, {%8,%9}, {%0,%1,%2,%3};"
                            : "+f"(acc[mf][nf][0]), "+f"(acc[mf][nf][1]),
                              "+f"(acc[mf][nf][2]), "+f"(acc[mf][nf][3])
                            : "r"(a[mf].x), "r"(a[mf].y), "r"(a[mf].z), "r"(a[mf].w),
                              "r"(b0[f]), "r"(b1[f]));
                    }
                }
            }
        }
    };

    // ---- mbarrier-handshook double-buffered mainloop (8 chunks) ----
    stage_load(0, 0);
    CPASYNC_MBAR_ARRIVE(mb_full0);
    stage_load(1, 1);
    CPASYNC_MBAR_ARRIVE(mb_full1);

#pragma unroll 1
    for (int c = 0; c < 8; ++c) {
        const int s = c & 1;
        const uint32_t fullb  = s ? mb_full1 : mb_full0;
        const uint32_t emptyb = s ? mb_empty1 : mb_empty0;
        const uint32_t par = (c >> 1) & 1;

        mbar_wait(fullb, par);
        compute(s);
        MBAR_ARRIVE(emptyb);
        if (c + 2 < 8) {
            mbar_wait(emptyb, par);
            stage_load(c + 2, s);
            CPASYNC_MBAR_ARRIVE(fullb);
        }
    }

    // ---- epilogue: demodulate + noise + bias ----
    float si[4][2], np[4][2], bp2[4][2];
#pragma unroll
    for (int mf = 0; mf < 4; ++mf)
#pragma unroll
        for (int hf = 0; hf < 2; ++hf) {
            int m = mwarp + mf * 16 + g + hf * 8;
            si[mf][hf]  = g_siginv[b * COUT + m];
            np[mf][hf]  = noise_param[m];
            bp2[mf][hf] = bias_param[m];
        }
#pragma unroll
    for (int nf = 0; nf < 8; ++nf) {
        int n  = nwarp + nf * 8 + q * 2;
        int wl = n >> 4;
        int t  = n & 15;
        float2 nz = *reinterpret_cast<const float2*>(
            noise + (((size_t)b * H_ + h) * W_ + w0 + wl) * T_ + t);
#pragma unroll
        for (int mf = 0; mf < 4; ++mf) {
#pragma unroll
            for (int hf = 0; hf < 2; ++hf) {
                int m = mwarp + mf * 16 + g + hf * 8;
                float2 r;
                r.x = acc[mf][nf][hf * 2 + 0] * si[mf][hf] + np[mf][hf] * nz.x + bp2[mf][hf];
                r.y = acc[mf][nf][hf * 2 + 1] * si[mf][hf] + np[mf][hf] * nz.y + bp2[mf][hf];
                *reinterpret_cast<float2*>(
                    out + ((((size_t)b * COUT + m) * H_ + h) * W_ + w0 + wl) * T_ + t) = r;
            }
        }
    }
}

// ---------------------------------------------------------------------------
// Launch. inputs: x, style, noise, weight, style_w, style_b, noise_param,
//                 bias_param
// ---------------------------------------------------------------------------
extern "C" void kernel_launch(void* const* d_in, const int* in_sizes, int n_in,
                              void* d_out, int out_size) {
    const float* x           = (const float*)d_in[0];
    const float* style       = (const float*)d_in[1];
    const float* noise       = (const float*)d_in[2];
    const float* weight      = (const float*)d_in[3];
    const float* style_w     = (const float*)d_in[4];
    const float* style_b     = (const float*)d_in[5];
    const float* noise_param = (const float*)d_in[6];
    const float* bias_param  = (const float*)d_in[7];
    float* out = (float*)d_out;

    k_style<<<64, 256>>>(style, style_w, style_b);
    k_w2<<<CIN, COUT>>>(weight);
    k_sig2<<<64, 256>>>();
    k_wfrag<<<dim3(72, B_), 256>>>(weight);
    // B_*8*4*(NPOS/2) units / 2 per thread = 2.097M threads -> 8192 x 256
    k_xpack<<<8192, 256>>>(x);

    cudaFuncSetAttribute(k_conv, cudaFuncAttributeMaxDynamicSharedMemorySize,
                         SMEM_BYTES);
    k_conv<<<2048, 128, SMEM_BYTES>>>(noise, noise_param, bias_param, out);
}